// round 3
// baseline (speedup 1.0000x reference)
#include <cuda_runtime.h>
#include <math.h>

// ---------------- problem constants ----------------
#define BATCH    2
#define SEQ      1024
#define DMODEL   1024
#define DINNER   2048
#define DSTATE   16
#define NTOK     (BATCH * SEQ)          // 2048
#define XW       (DINNER + 2 * DSTATE) // 2080 (x_ssm width)

// ---------------- scratch (static device globals; no allocation) --------
__device__ float g_xn [NTOK * DMODEL];        // rmsnorm output         [2048,1024]
__device__ float g_xr [NTOK * 2 * DINNER];    // in_proj output         [2048,4096]
__device__ float g_xs [NTOK * DINNER];        // conv+silu output       [2048,2048]
__device__ float g_ssm[NTOK * XW];            // x_proj output          [2048,2080]
__device__ float g_dt [NTOK * DINNER];        // softplus(dt@W_dt)      [2048,2048]
__device__ float g_yz [NTOK * DINNER];        // y * silu(res)          [2048,2048]

// ---------------- f32x2 packed-math helpers ----------------
__device__ __forceinline__ unsigned long long pk2(float lo, float hi) {
    unsigned long long r;
    asm("mov.b64 %0, {%1, %2};" : "=l"(r) : "f"(lo), "f"(hi));
    return r;
}
__device__ __forceinline__ void upk2(unsigned long long v, float& lo, float& hi) {
    asm("mov.b64 {%0, %1}, %2;" : "=f"(lo), "=f"(hi) : "l"(v));
}

// ---------------- RMSNorm ----------------
__global__ void rmsnorm_kernel(const float* __restrict__ x,
                               const float* __restrict__ w,
                               float* __restrict__ xn) {
    const int t   = blockIdx.x;            // token
    const int tid = threadIdx.x;           // 256 threads, each handles 4 elems
    const float4 v = reinterpret_cast<const float4*>(x + t * DMODEL)[tid];
    float s = v.x * v.x + v.y * v.y + v.z * v.z + v.w * v.w;
    #pragma unroll
    for (int o = 16; o; o >>= 1) s += __shfl_xor_sync(0xffffffffu, s, o);
    __shared__ float red[8];
    __shared__ float sscale;
    if ((tid & 31) == 0) red[tid >> 5] = s;
    __syncthreads();
    if (tid == 0) {
        float tot = 0.f;
        #pragma unroll
        for (int i = 0; i < 8; ++i) tot += red[i];
        sscale = rsqrtf(tot * (1.0f / DMODEL) + 1e-5f);
    }
    __syncthreads();
    const float sc = sscale;
    const float4 wv = reinterpret_cast<const float4*>(w)[tid];
    float4 o;
    o.x = v.x * sc * wv.x;
    o.y = v.y * sc * wv.y;
    o.z = v.z * sc * wv.z;
    o.w = v.w * sc * wv.w;
    reinterpret_cast<float4*>(xn + t * DMODEL)[tid] = o;
}

// ---------------- depthwise causal conv (d_conv=4) + SiLU ----------------
__global__ void conv_silu_kernel(const float* __restrict__ xr,
                                 const float* __restrict__ cw,
                                 const float* __restrict__ cb,
                                 float* __restrict__ xs) {
    const int idx = blockIdx.x * blockDim.x + threadIdx.x; // 0 .. NTOK*DINNER-1
    const int d   = idx & (DINNER - 1);
    const int tok = idx >> 11;
    const int l   = tok & (SEQ - 1);
    float acc = cb[d];
    #pragma unroll
    for (int j = 0; j < 4; ++j) {
        const int ls = l - 3 + j;
        if (ls >= 0)
            acc = fmaf(cw[d * 4 + j], xr[(tok + j - 3) * (2 * DINNER) + d], acc);
    }
    xs[idx] = acc / (1.f + __expf(-acc));   // silu
}

// ---------------- generic tiled fp32 GEMM (f32x2 packed FMA) ----------------
// D[M,N] = act( A[M,K](lda) @ B[K,N](ldb) )   (+ Res for ACT_RESADD)
// BM=BN=128, BK=16, 256 threads, 8x8 micro-tile per thread (cols split 4+4).
#define BM 128
#define BN 128
#define BK 16
#define SPAD 4

#define ACT_NONE     0
#define ACT_SOFTPLUS 1
#define ACT_RESADD   2

template <int ACT>
__global__ __launch_bounds__(256, 2)
void gemm_kernel(const float* __restrict__ A, const float* __restrict__ B,
                 float* __restrict__ D, const float* __restrict__ Res,
                 int M, int N, int K, int lda, int ldb, int ldd, int ldr) {
    __shared__ float As[BK][BM + SPAD];
    __shared__ float Bs[BK][BN + SPAD];

    const int tid = threadIdx.x;
    const int tx  = tid & 15;     // 16 col groups
    const int ty  = tid >> 4;     // 16 row groups
    const int m0  = blockIdx.y * BM;
    const int n0  = blockIdx.x * BN;

    // A load: 2 x float4 per thread, transposed store into As[k][m]
    const int arow = tid >> 2;         // 0..63
    const int acol = (tid & 3) << 2;   // 0,4,8,12
    // B load: 2 x float4 per thread
    const int brow = tid >> 5;         // 0..7
    const int bcol = (tid & 31) << 2;  // 0..124
    const bool bok = (n0 + bcol) < N;  // N is always a multiple of 4

    unsigned long long acc[8][4];
    #pragma unroll
    for (int i = 0; i < 8; ++i)
        #pragma unroll
        for (int j = 0; j < 4; ++j) acc[i][j] = 0ULL;

    for (int k0 = 0; k0 < K; k0 += BK) {
        const float4 av0 = *reinterpret_cast<const float4*>(
            &A[(m0 + arow) * lda + k0 + acol]);
        const float4 av1 = *reinterpret_cast<const float4*>(
            &A[(m0 + arow + 64) * lda + k0 + acol]);
        float4 bv0 = make_float4(0.f, 0.f, 0.f, 0.f);
        float4 bv1 = bv0;
        if (bok) {
            bv0 = *reinterpret_cast<const float4*>(&B[(k0 + brow) * ldb + n0 + bcol]);
            bv1 = *reinterpret_cast<const float4*>(&B[(k0 + brow + 8) * ldb + n0 + bcol]);
        }
        __syncthreads();
        As[acol + 0][arow] = av0.x;  As[acol + 1][arow] = av0.y;
        As[acol + 2][arow] = av0.z;  As[acol + 3][arow] = av0.w;
        As[acol + 0][arow + 64] = av1.x;  As[acol + 1][arow + 64] = av1.y;
        As[acol + 2][arow + 64] = av1.z;  As[acol + 3][arow + 64] = av1.w;
        *reinterpret_cast<float4*>(&Bs[brow][bcol])     = bv0;
        *reinterpret_cast<float4*>(&Bs[brow + 8][bcol]) = bv1;
        __syncthreads();

        #pragma unroll
        for (int k = 0; k < BK; ++k) {
            const float4 a0 = *reinterpret_cast<const float4*>(&As[k][ty * 8]);
            const float4 a1 = *reinterpret_cast<const float4*>(&As[k][ty * 8 + 4]);
            const float4 b0 = *reinterpret_cast<const float4*>(&Bs[k][tx * 4]);
            const float4 b1 = *reinterpret_cast<const float4*>(&Bs[k][tx * 4 + 64]);
            unsigned long long b2[4];
            b2[0] = pk2(b0.x, b0.y);  b2[1] = pk2(b0.z, b0.w);
            b2[2] = pk2(b1.x, b1.y);  b2[3] = pk2(b1.z, b1.w);
            const float a[8] = {a0.x, a0.y, a0.z, a0.w, a1.x, a1.y, a1.z, a1.w};
            #pragma unroll
            for (int i = 0; i < 8; ++i) {
                const unsigned long long a2 = pk2(a[i], a[i]);
                #pragma unroll
                for (int j = 0; j < 4; ++j)
                    asm("fma.rn.f32x2 %0, %1, %2, %0;"
                        : "+l"(acc[i][j]) : "l"(a2), "l"(b2[j]));
            }
        }
    }

    // epilogue
    #pragma unroll
    for (int i = 0; i < 8; ++i) {
        const int row = m0 + ty * 8 + i;
        float c[8];
        upk2(acc[i][0], c[0], c[1]);  upk2(acc[i][1], c[2], c[3]);
        upk2(acc[i][2], c[4], c[5]);  upk2(acc[i][3], c[6], c[7]);
        const int c0 = n0 + tx * 4;
        const int c1 = n0 + 64 + tx * 4;
        if (ACT == ACT_SOFTPLUS) {
            #pragma unroll
            for (int j = 0; j < 8; ++j)
                c[j] = fmaxf(c[j], 0.f) + log1pf(__expf(-fabsf(c[j])));
        }
        if (ACT == ACT_RESADD) {
            if (c0 < N) {
                const float4 r = *reinterpret_cast<const float4*>(&Res[row * ldr + c0]);
                c[0] += r.x; c[1] += r.y; c[2] += r.z; c[3] += r.w;
            }
            if (c1 < N) {
                const float4 r = *reinterpret_cast<const float4*>(&Res[row * ldr + c1]);
                c[4] += r.x; c[5] += r.y; c[6] += r.z; c[7] += r.w;
            }
        }
        if (c0 < N)
            *reinterpret_cast<float4*>(&D[row * ldd + c0]) =
                make_float4(c[0], c[1], c[2], c[3]);
        if (c1 < N)
            *reinterpret_cast<float4*>(&D[row * ldd + c1]) =
                make_float4(c[4], c[5], c[6], c[7]);
    }
}

// ---------------- selective scan (sequential over L) ----------------
// lane layout: warp handles 2 adjacent (b,d) pairs; 16 lanes (one per state n)
// per pair. Both halves of a warp share the same (b,l) token.
// Fuses y * silu(res) into the store.
__global__ void scan_kernel(const float* __restrict__ dt,
                            const float* __restrict__ xs,
                            const float* __restrict__ ssm,
                            const float* __restrict__ xr,
                            const float* __restrict__ A_log,
                            float* __restrict__ yz) {
    const int wg   = (blockIdx.x * blockDim.x + threadIdx.x) >> 5;  // 0..2047
    const int lane = threadIdx.x & 31;
    const int half = lane >> 4;
    const int n    = lane & 15;
    const int p    = 2 * wg + half;   // (b,d) pair index: both halves same b
    const int b    = p >> 11;
    const int d    = p & (DINNER - 1);

    const float Acoef = -__expf(A_log[d * DSTATE + n]);
    float h = 0.f;
    const int tokbase = b * SEQ;

    for (int l = 0; l < SEQ; ++l) {
        const int tok = tokbase + l;
        const float dtv = __ldg(&dt[tok * DINNER + d]);
        const float xv  = __ldg(&xs[tok * DINNER + d]);
        const float Bv  = __ldg(&ssm[tok * XW + DINNER + n]);
        const float Cv  = __ldg(&ssm[tok * XW + DINNER + DSTATE + n]);
        const float Ad  = __expf(Acoef * dtv);
        h = fmaf(Ad, h, dtv * Bv * xv);
        float v = h * Cv;
        v += __shfl_xor_sync(0xffffffffu, v, 8);
        v += __shfl_xor_sync(0xffffffffu, v, 4);
        v += __shfl_xor_sync(0xffffffffu, v, 2);
        v += __shfl_xor_sync(0xffffffffu, v, 1);
        if (n == 0) {
            const float r = xr[tok * (2 * DINNER) + DINNER + d];  // res (pre-act)
            yz[tok * DINNER + d] = v * (r / (1.f + __expf(-r)));  // y * silu(res)
        }
    }
}

// ---------------- launch ----------------
extern "C" void kernel_launch(void* const* d_in, const int* in_sizes, int n_in,
                              void* d_out, int out_size) {
    const float* x      = (const float*)d_in[0];  // [2,1024,1024]
    const float* rms_w  = (const float*)d_in[1];  // [1024]
    const float* W_in   = (const float*)d_in[2];  // [1024,4096]
    const float* conv_w = (const float*)d_in[3];  // [2048,1,4]
    const float* conv_b = (const float*)d_in[4];  // [2048]
    const float* W_x    = (const float*)d_in[5];  // [2048,2080]
    const float* W_dt   = (const float*)d_in[6];  // [2048,2048]
    const float* A_log  = (const float*)d_in[7];  // [2048,16]
    const float* W_out  = (const float*)d_in[8];  // [2048,1024]
    float* out = (float*)d_out;                   // [2,1024,1024] fp32

    float *xn, *xr, *xs, *ssm, *dtb, *yz;
    cudaGetSymbolAddress((void**)&xn,  g_xn);
    cudaGetSymbolAddress((void**)&xr,  g_xr);
    cudaGetSymbolAddress((void**)&xs,  g_xs);
    cudaGetSymbolAddress((void**)&ssm, g_ssm);
    cudaGetSymbolAddress((void**)&dtb, g_dt);
    cudaGetSymbolAddress((void**)&yz,  g_yz);

    // 1. RMSNorm
    rmsnorm_kernel<<<NTOK, 256>>>(x, rms_w, xn);

    // 2. xr = xn @ W_in          [2048,4096]
    gemm_kernel<ACT_NONE><<<dim3(4096 / BN, NTOK / BM), 256>>>(
        xn, W_in, xr, nullptr, NTOK, 4096, DMODEL, DMODEL, 4096, 4096, 0);

    // 3. depthwise conv + silu   [2048,2048]
    conv_silu_kernel<<<(NTOK * DINNER) / 256, 256>>>(xr, conv_w, conv_b, xs);

    // 4. x_ssm = xs @ W_x        [2048,2080]  (17 tiles along N, edge guarded)
    gemm_kernel<ACT_NONE><<<dim3((XW + BN - 1) / BN, NTOK / BM), 256>>>(
        xs, W_x, ssm, nullptr, NTOK, XW, DINNER, DINNER, XW, XW, 0);

    // 5. dt = softplus(x_ssm[:, :2048] @ W_dt)   [2048,2048]
    gemm_kernel<ACT_SOFTPLUS><<<dim3(DINNER / BN, NTOK / BM), 256>>>(
        ssm, W_dt, dtb, nullptr, NTOK, DINNER, DINNER, XW, DINNER, DINNER, 0);

    // 6. selective scan, fused with y * silu(res)   [2048,2048]
    scan_kernel<<<(2 * NTOK * DINNER / DSTATE) / 256 / 8 * 8 / 8, 256>>>(
        dtb, xs, ssm, xr, A_log, yz);
    // note: grid = 2048 warps / 8 warps-per-block = 256 blocks
    // (expression above evaluates to 256)

    // 7. out = x + yz @ W_out    [2048,1024]
    gemm_kernel<ACT_RESADD><<<dim3(DMODEL / BN, NTOK / BM), 256>>>(
        yz, W_out, out, x, NTOK, DMODEL, DINNER, DINNER, DMODEL, DMODEL, DMODEL);
}

// round 4
// speedup vs baseline: 1.8435x; 1.8435x over previous
#include <cuda_runtime.h>
#include <math.h>

// ---------------- problem constants ----------------
#define BATCH    2
#define SEQ      1024
#define DMODEL   1024
#define DINNER   2048
#define DSTATE   16
#define NTOK     (BATCH * SEQ)          // 2048
#define XW       (DINNER + 2 * DSTATE)  // 2080
#define NSEG     32
#define GSEG     32                     // SEQ / NSEG

// ---------------- scratch ----------------
__device__ float g_xn [NTOK * DMODEL];
__device__ float g_xr [NTOK * 2 * DINNER];
__device__ float g_xs [NTOK * DINNER];
__device__ float g_ssm[NTOK * XW];
__device__ float g_dt [NTOK * DINNER];
__device__ float g_yz [NTOK * DINNER];
__device__ float g_P  [BATCH * NSEG * DSTATE * DINNER];
__device__ float g_Q  [BATCH * NSEG * DSTATE * DINNER];
__device__ float g_H  [BATCH * NSEG * DSTATE * DINNER];

// ---------------- helpers ----------------
__device__ __forceinline__ unsigned long long pk2(float lo, float hi) {
    unsigned long long r;
    asm("mov.b64 %0, {%1, %2};" : "=l"(r) : "f"(lo), "f"(hi));
    return r;
}
__device__ __forceinline__ void upk2(unsigned long long v, float& lo, float& hi) {
    asm("mov.b64 {%0, %1}, %2;" : "=f"(lo), "=f"(hi) : "l"(v));
}
__device__ __forceinline__ void cp_async16(void* sptr, const void* gptr) {
    unsigned int saddr = (unsigned int)__cvta_generic_to_shared(sptr);
    asm volatile("cp.async.cg.shared.global [%0], [%1], 16;\n"
                 :: "r"(saddr), "l"(gptr));
}
__device__ __forceinline__ void cp_commit() {
    asm volatile("cp.async.commit_group;\n");
}
__device__ __forceinline__ void cp_wait1() {
    asm volatile("cp.async.wait_group 1;\n" ::: "memory");
}

// ---------------- RMSNorm ----------------
__global__ void rmsnorm_kernel(const float* __restrict__ x,
                               const float* __restrict__ w,
                               float* __restrict__ xn) {
    const int t   = blockIdx.x;
    const int tid = threadIdx.x;
    const float4 v = reinterpret_cast<const float4*>(x + t * DMODEL)[tid];
    float s = v.x * v.x + v.y * v.y + v.z * v.z + v.w * v.w;
    #pragma unroll
    for (int o = 16; o; o >>= 1) s += __shfl_xor_sync(0xffffffffu, s, o);
    __shared__ float red[8];
    __shared__ float sscale;
    if ((tid & 31) == 0) red[tid >> 5] = s;
    __syncthreads();
    if (tid == 0) {
        float tot = 0.f;
        #pragma unroll
        for (int i = 0; i < 8; ++i) tot += red[i];
        sscale = rsqrtf(tot * (1.0f / DMODEL) + 1e-5f);
    }
    __syncthreads();
    const float sc = sscale;
    const float4 wv = reinterpret_cast<const float4*>(w)[tid];
    float4 o;
    o.x = v.x * sc * wv.x;  o.y = v.y * sc * wv.y;
    o.z = v.z * sc * wv.z;  o.w = v.w * sc * wv.w;
    reinterpret_cast<float4*>(xn + t * DMODEL)[tid] = o;
}

// ---------------- depthwise causal conv (d_conv=4) + SiLU ----------------
__global__ void conv_silu_kernel(const float* __restrict__ xr,
                                 const float* __restrict__ cw,
                                 const float* __restrict__ cb,
                                 float* __restrict__ xs) {
    const int idx = blockIdx.x * blockDim.x + threadIdx.x;
    const int d   = idx & (DINNER - 1);
    const int tok = idx >> 11;
    const int l   = tok & (SEQ - 1);
    float acc = cb[d];
    #pragma unroll
    for (int j = 0; j < 4; ++j) {
        const int ls = l - 3 + j;
        if (ls >= 0)
            acc = fmaf(cw[d * 4 + j], xr[(tok + j - 3) * (2 * DINNER) + d], acc);
    }
    xs[idx] = acc / (1.f + __expf(-acc));
}

// ---------------- tiled fp32 GEMM, 3-stage cp.async pipeline ----------------
#define BM 128
#define BN 128
#define BK 16
#define SPAD 4

#define ACT_NONE     0
#define ACT_SOFTPLUS 1
#define ACT_RESADD   2

template <int ACT>
__global__ __launch_bounds__(256, 2)
void gemm_kernel(const float* __restrict__ A, const float* __restrict__ B,
                 float* __restrict__ D, const float* __restrict__ Res,
                 int N, int K, int lda, int ldb, int ldd, int ldr) {
    __shared__ float As[2][BK][BM + SPAD];   // reg->STS pipeline, 2 stages
    __shared__ float Bs[3][BK][BN + SPAD];   // cp.async pipeline, 3 stages

    const int tid = threadIdx.x;
    const int tx  = tid & 15;
    const int ty  = tid >> 4;
    const int m0  = blockIdx.y * BM;
    const int n0  = blockIdx.x * BN;

    const int arow = tid >> 2;          // 0..63
    const int acol = (tid & 3) << 2;    // 0,4,8,12
    const int brow = tid >> 5;          // 0..7
    const int bcol = (tid & 31) << 2;   // 0..124
    const bool bok = (n0 + bcol) < N;

    // OOB B slots: zero once; never overwritten by cp.async afterwards.
    if (!bok) {
        #pragma unroll
        for (int st = 0; st < 3; ++st) {
            *reinterpret_cast<float4*>(&Bs[st][brow][bcol])     = make_float4(0,0,0,0);
            *reinterpret_cast<float4*>(&Bs[st][brow + 8][bcol]) = make_float4(0,0,0,0);
        }
    }

    const float* Ag = A + m0 * lda;
    const int T = K / BK;

    // ---- prolog: A tile0 -> smem, A tile1 -> regs, B tiles 0,1 via cp.async
    float4 av0 = *reinterpret_cast<const float4*>(&Ag[arow * lda + acol]);
    float4 av1 = *reinterpret_cast<const float4*>(&Ag[(arow + 64) * lda + acol]);
    As[0][acol + 0][arow] = av0.x;  As[0][acol + 1][arow] = av0.y;
    As[0][acol + 2][arow] = av0.z;  As[0][acol + 3][arow] = av0.w;
    As[0][acol + 0][arow + 64] = av1.x;  As[0][acol + 1][arow + 64] = av1.y;
    As[0][acol + 2][arow + 64] = av1.z;  As[0][acol + 3][arow + 64] = av1.w;
    av0 = *reinterpret_cast<const float4*>(&Ag[arow * lda + BK + acol]);
    av1 = *reinterpret_cast<const float4*>(&Ag[(arow + 64) * lda + BK + acol]);

    if (bok) {
        cp_async16(&Bs[0][brow][bcol],     &B[brow * ldb + n0 + bcol]);
        cp_async16(&Bs[0][brow + 8][bcol], &B[(brow + 8) * ldb + n0 + bcol]);
    }
    cp_commit();
    if (bok) {
        cp_async16(&Bs[1][brow][bcol],     &B[(BK + brow) * ldb + n0 + bcol]);
        cp_async16(&Bs[1][brow + 8][bcol], &B[(BK + brow + 8) * ldb + n0 + bcol]);
    }
    cp_commit();

    unsigned long long acc[8][4];
    #pragma unroll
    for (int i = 0; i < 8; ++i)
        #pragma unroll
        for (int j = 0; j < 4; ++j) acc[i][j] = 0ULL;

    for (int i = 0; i < T; ++i) {
        cp_wait1();          // B tile i resident
        __syncthreads();     // everyone done with tile i-1 buffers; tile-i data visible

        if (i + 1 < T) {     // stash A tile i+1 (held in regs) into the other As buffer
            const int ab = (i + 1) & 1;
            As[ab][acol + 0][arow] = av0.x;  As[ab][acol + 1][arow] = av0.y;
            As[ab][acol + 2][arow] = av0.z;  As[ab][acol + 3][arow] = av0.w;
            As[ab][acol + 0][arow + 64] = av1.x;  As[ab][acol + 1][arow + 64] = av1.y;
            As[ab][acol + 2][arow + 64] = av1.z;  As[ab][acol + 3][arow + 64] = av1.w;
        }
        if (i + 2 < T) {     // start fetching tile i+2
            av0 = *reinterpret_cast<const float4*>(&Ag[arow * lda + (i + 2) * BK + acol]);
            av1 = *reinterpret_cast<const float4*>(&Ag[(arow + 64) * lda + (i + 2) * BK + acol]);
            if (bok) {
                const int bsn = (i + 2) % 3;
                cp_async16(&Bs[bsn][brow][bcol],
                           &B[((i + 2) * BK + brow) * ldb + n0 + bcol]);
                cp_async16(&Bs[bsn][brow + 8][bcol],
                           &B[((i + 2) * BK + brow + 8) * ldb + n0 + bcol]);
            }
        }
        cp_commit();

        const int ab = i & 1, bs = i % 3;
        #pragma unroll
        for (int k = 0; k < BK; ++k) {
            const float4 a0 = *reinterpret_cast<const float4*>(&As[ab][k][ty * 8]);
            const float4 a1 = *reinterpret_cast<const float4*>(&As[ab][k][ty * 8 + 4]);
            const ulonglong2 bA = *reinterpret_cast<const ulonglong2*>(&Bs[bs][k][tx * 4]);
            const ulonglong2 bB = *reinterpret_cast<const ulonglong2*>(&Bs[bs][k][tx * 4 + 64]);
            const unsigned long long b2[4] = {bA.x, bA.y, bB.x, bB.y};
            const float a[8] = {a0.x, a0.y, a0.z, a0.w, a1.x, a1.y, a1.z, a1.w};
            #pragma unroll
            for (int r = 0; r < 8; ++r) {
                const unsigned long long a2 = pk2(a[r], a[r]);
                #pragma unroll
                for (int j = 0; j < 4; ++j)
                    asm("fma.rn.f32x2 %0, %1, %2, %0;"
                        : "+l"(acc[r][j]) : "l"(a2), "l"(b2[j]));
            }
        }
    }

    // ---- epilogue
    #pragma unroll
    for (int i = 0; i < 8; ++i) {
        const int row = m0 + ty * 8 + i;
        float c[8];
        upk2(acc[i][0], c[0], c[1]);  upk2(acc[i][1], c[2], c[3]);
        upk2(acc[i][2], c[4], c[5]);  upk2(acc[i][3], c[6], c[7]);
        const int c0 = n0 + tx * 4;
        const int c1 = n0 + 64 + tx * 4;
        if (ACT == ACT_SOFTPLUS) {
            #pragma unroll
            for (int j = 0; j < 8; ++j)
                c[j] = fmaxf(c[j], 0.f) + log1pf(__expf(-fabsf(c[j])));
        }
        if (ACT == ACT_RESADD) {
            if (c0 < N) {
                const float4 r = *reinterpret_cast<const float4*>(&Res[row * ldr + c0]);
                c[0] += r.x; c[1] += r.y; c[2] += r.z; c[3] += r.w;
            }
            if (c1 < N) {
                const float4 r = *reinterpret_cast<const float4*>(&Res[row * ldr + c1]);
                c[4] += r.x; c[5] += r.y; c[6] += r.z; c[7] += r.w;
            }
        }
        if (c0 < N)
            *reinterpret_cast<float4*>(&D[row * ldd + c0]) =
                make_float4(c[0], c[1], c[2], c[3]);
        if (c1 < N)
            *reinterpret_cast<float4*>(&D[row * ldd + c1]) =
                make_float4(c[4], c[5], c[6], c[7]);
    }
}

// ---------------- chunked parallel selective scan ----------------
// off(b,s,n,d) = ((b*NSEG+s)*DSTATE + n)*DINNER + d

// Pass 1: per (b,d,segment) thread runs the recurrence with h0=0 -> Q,
// and P = exp(Acoef * sum(dt)) (exact product of the per-step decays).
__global__ __launch_bounds__(256)
void scan_p1(const float* __restrict__ dt, const float* __restrict__ xs,
             const float* __restrict__ ssm, const float* __restrict__ A_log,
             float* __restrict__ P, float* __restrict__ Q) {
    __shared__ float Bsh[GSEG][DSTATE];
    const int b = blockIdx.z, s = blockIdx.y;
    const int d = blockIdx.x * 256 + threadIdx.x;
    const int tok0 = b * SEQ + s * GSEG;

    for (int v = threadIdx.x; v < GSEG * DSTATE; v += 256) {
        const int l = v >> 4, n = v & 15;
        Bsh[l][n] = ssm[(tok0 + l) * XW + DINNER + n];
    }
    __syncthreads();

    float Ac[DSTATE];
    #pragma unroll
    for (int q = 0; q < 4; ++q) {
        const float4 v = reinterpret_cast<const float4*>(&A_log[d * DSTATE])[q];
        Ac[4 * q + 0] = -__expf(v.x);  Ac[4 * q + 1] = -__expf(v.y);
        Ac[4 * q + 2] = -__expf(v.z);  Ac[4 * q + 3] = -__expf(v.w);
    }

    float h[DSTATE];
    #pragma unroll
    for (int n = 0; n < DSTATE; ++n) h[n] = 0.f;
    float sdt = 0.f;

    for (int l = 0; l < GSEG; ++l) {
        const float dtv = dt[(tok0 + l) * DINNER + d];
        const float xv  = xs[(tok0 + l) * DINNER + d];
        sdt += dtv;
        const float dtx = dtv * xv;
        #pragma unroll
        for (int n = 0; n < DSTATE; ++n)
            h[n] = fmaf(__expf(Ac[n] * dtv), h[n], dtx * Bsh[l][n]);
    }

    const int base = ((b * NSEG + s) * DSTATE) * DINNER + d;
    #pragma unroll
    for (int n = 0; n < DSTATE; ++n) {
        P[base + n * DINNER] = __expf(Ac[n] * sdt);
        Q[base + n * DINNER] = h[n];
    }
}

// Combine: exclusive affine scan over the 32 segments per (b,n,d).
__global__ void scan_combine(const float* __restrict__ P,
                             const float* __restrict__ Q,
                             float* __restrict__ H) {
    const int t = blockIdx.x * 256 + threadIdx.x;   // 65536
    const int d = t & (DINNER - 1);
    const int n = (t >> 11) & 15;
    const int b = t >> 15;
    float h = 0.f;
    for (int s = 0; s < NSEG; ++s) {
        const int off = ((b * NSEG + s) * DSTATE + n) * DINNER + d;
        H[off] = h;
        h = fmaf(P[off], h, Q[off]);
    }
}

// Pass 2: replay each segment from its true initial state; emit y * silu(res).
__global__ __launch_bounds__(256)
void scan_p2(const float* __restrict__ dt, const float* __restrict__ xs,
             const float* __restrict__ ssm, const float* __restrict__ xr,
             const float* __restrict__ A_log, const float* __restrict__ H,
             float* __restrict__ yz) {
    __shared__ float Bsh[GSEG][DSTATE];
    __shared__ float Csh[GSEG][DSTATE];
    const int b = blockIdx.z, s = blockIdx.y;
    const int d = blockIdx.x * 256 + threadIdx.x;
    const int tok0 = b * SEQ + s * GSEG;

    for (int v = threadIdx.x; v < GSEG * DSTATE * 2; v += 256) {
        const int l = v >> 5, j = v & 31;
        const float val = ssm[(tok0 + l) * XW + DINNER + j];
        if (j < DSTATE) Bsh[l][j] = val;
        else            Csh[l][j - DSTATE] = val;
    }
    __syncthreads();

    float Ac[DSTATE];
    #pragma unroll
    for (int q = 0; q < 4; ++q) {
        const float4 v = reinterpret_cast<const float4*>(&A_log[d * DSTATE])[q];
        Ac[4 * q + 0] = -__expf(v.x);  Ac[4 * q + 1] = -__expf(v.y);
        Ac[4 * q + 2] = -__expf(v.z);  Ac[4 * q + 3] = -__expf(v.w);
    }

    const int base = ((b * NSEG + s) * DSTATE) * DINNER + d;
    float h[DSTATE];
    #pragma unroll
    for (int n = 0; n < DSTATE; ++n) h[n] = H[base + n * DINNER];

    for (int l = 0; l < GSEG; ++l) {
        const float dtv = dt[(tok0 + l) * DINNER + d];
        const float xv  = xs[(tok0 + l) * DINNER + d];
        const float dtx = dtv * xv;
        float y = 0.f;
        #pragma unroll
        for (int n = 0; n < DSTATE; ++n) {
            h[n] = fmaf(__expf(Ac[n] * dtv), h[n], dtx * Bsh[l][n]);
            y = fmaf(h[n], Csh[l][n], y);
        }
        const float r = xr[(tok0 + l) * (2 * DINNER) + DINNER + d];
        yz[(tok0 + l) * DINNER + d] = y * (r / (1.f + __expf(-r)));
    }
}

// ---------------- launch ----------------
extern "C" void kernel_launch(void* const* d_in, const int* in_sizes, int n_in,
                              void* d_out, int out_size) {
    const float* x      = (const float*)d_in[0];
    const float* rms_w  = (const float*)d_in[1];
    const float* W_in   = (const float*)d_in[2];
    const float* conv_w = (const float*)d_in[3];
    const float* conv_b = (const float*)d_in[4];
    const float* W_x    = (const float*)d_in[5];
    const float* W_dt   = (const float*)d_in[6];
    const float* A_log  = (const float*)d_in[7];
    const float* W_out  = (const float*)d_in[8];
    float* out = (float*)d_out;

    float *xn, *xr, *xs, *ssm, *dtb, *yz, *P, *Q, *H;
    cudaGetSymbolAddress((void**)&xn,  g_xn);
    cudaGetSymbolAddress((void**)&xr,  g_xr);
    cudaGetSymbolAddress((void**)&xs,  g_xs);
    cudaGetSymbolAddress((void**)&ssm, g_ssm);
    cudaGetSymbolAddress((void**)&dtb, g_dt);
    cudaGetSymbolAddress((void**)&yz,  g_yz);
    cudaGetSymbolAddress((void**)&P,   g_P);
    cudaGetSymbolAddress((void**)&Q,   g_Q);
    cudaGetSymbolAddress((void**)&H,   g_H);

    // 1. RMSNorm
    rmsnorm_kernel<<<NTOK, 256>>>(x, rms_w, xn);

    // 2. xr = xn @ W_in          [2048,4096]
    gemm_kernel<ACT_NONE><<<dim3(4096 / BN, NTOK / BM), 256>>>(
        xn, W_in, xr, nullptr, 4096, DMODEL, DMODEL, 4096, 4096, 0);

    // 3. depthwise conv + silu   [2048,2048]
    conv_silu_kernel<<<(NTOK * DINNER) / 256, 256>>>(xr, conv_w, conv_b, xs);

    // 4. x_ssm = xs @ W_x        [2048,2080]
    gemm_kernel<ACT_NONE><<<dim3((XW + BN - 1) / BN, NTOK / BM), 256>>>(
        xs, W_x, ssm, nullptr, XW, DINNER, DINNER, XW, XW, 0);

    // 5. dt = softplus(x_ssm[:, :2048] @ W_dt)
    gemm_kernel<ACT_SOFTPLUS><<<dim3(DINNER / BN, NTOK / BM), 256>>>(
        ssm, W_dt, dtb, nullptr, DINNER, DINNER, XW, DINNER, DINNER, 0);

    // 6. chunked parallel scan
    scan_p1<<<dim3(DINNER / 256, NSEG, BATCH), 256>>>(dtb, xs, ssm, A_log, P, Q);
    scan_combine<<<(BATCH * DSTATE * DINNER) / 256, 256>>>(P, Q, H);
    scan_p2<<<dim3(DINNER / 256, NSEG, BATCH), 256>>>(dtb, xs, ssm, xr, A_log, H, yz);

    // 7. out = x + yz @ W_out
    gemm_kernel<ACT_RESADD><<<dim3(DMODEL / BN, NTOK / BM), 256>>>(
        yz, W_out, out, x, DMODEL, DINNER, DINNER, DMODEL, DMODEL, DMODEL);
}